// round 10
// baseline (speedup 1.0000x reference)
#include <cuda_runtime.h>
#include <math.h>
#include <stdint.h>

#define BATCH  4
#define SEQ    4096
#define DMODEL 1024
#define DINNER 2048
#define DSTATE 16
#define NTOK   (BATCH*SEQ)     // 16384
#define SCHUNK 64
#define NCHUNK (SEQ/SCHUNK)    // 64
#define NSPLIT 4
#define KSPL   (DINNER/NSPLIT) // 512

// ---- scratch (device globals; no allocations allowed) ----
__device__ float g_xmain[(size_t)NTOK*DINNER];
__device__ float g_sres [(size_t)NTOK*DINNER];
__device__ float g_xc   [(size_t)NTOK*DINNER];
__device__ float g_y    [(size_t)NTOK*DINNER];     // packed-A tf32 (gate output)
__device__ float g_xr   [(size_t)NTOK*DMODEL];     // packed-A tf32 x
__device__ float g_win  [(size_t)2*DINNER*DMODEL]; // packed-B tf32 W_in^T
__device__ float g_wout [(size_t)DMODEL*DINNER];   // packed-B tf32 W_out^T
__device__ float g_part [(size_t)NSPLIT*NTOK*32];  // partial B/C projections
__device__ float g_B    [NTOK*DSTATE];
__device__ float g_C    [NTOK*DSTATE];
__device__ float g_loc  [NTOK*DSTATE];
__device__ float g_E    [BATCH*NCHUNK*DSTATE];
__device__ float g_Sinit[BATCH*NCHUNK*DSTATE];
__device__ float g_ys   [NTOK];
__device__ float g_decay[DSTATE];
__device__ float g_dCH  [DSTATE];
__device__ float g_l2d  [DSTATE];

__device__ __forceinline__ float silu(float v) { return v / (1.f + __expf(-v)); }
__device__ __forceinline__ uint32_t f2tf(float x) {
    uint32_t r; asm("cvt.rna.tf32.f32 %0, %1;" : "=r"(r) : "f"(x)); return r;
}

// ============================================================================
// Fragment-packed layouts for mma.sync.m16n8k8 (row.col).
// ============================================================================
__device__ __forceinline__ int a_idx_local(int mi, int ki) {
    int wm = mi >> 6, r6 = mi & 63, mf = r6 >> 4, rr = mi & 15;
    int gid = rr & 7, rowhalf = rr >> 3;
    int ks = ki >> 3, k8 = ki & 7, tig = k8 & 3, khalf = k8 >> 2;
    int lane = gid * 4 + tig, comp = rowhalf + 2 * khalf;
    return (((ks * 2 + wm) * 4 + mf) * 32 + lane) * 4 + comp;
}
__device__ __forceinline__ int b_idx_local(int ni, int ki) {
    int wn = ni >> 6, r6 = ni & 63, nf = r6 >> 3, gid = r6 & 7;
    int j = nf >> 1, nhalf = nf & 1;
    int ks = ki >> 3, k8 = ki & 7, tig = k8 & 3, khalf = k8 >> 2;
    int lane = gid * 4 + tig, comp = nhalf * 2 + khalf;
    return (((ks * 2 + wn) * 4 + j) * 32 + lane) * 4 + comp;
}

// ---- x -> packed-A tf32, smem-staged ----
__global__ __launch_bounds__(256) void pack_a_kernel(
    const float* __restrict__ in, float* __restrict__ out, int K)
{
    __shared__ float spk[4096];
    const int tid = threadIdx.x;
    const int ch0 = blockIdx.x * 32, m0 = blockIdx.y * 128;
    const int col4 = tid & 7, r0 = tid >> 3;
    #pragma unroll
    for (int rep = 0; rep < 4; rep++) {
        int r = r0 + rep * 32;
        float4 v = *(const float4*)&in[(size_t)(m0 + r) * K + ch0 + col4 * 4];
        spk[a_idx_local(r, col4 * 4 + 0)] = __uint_as_float(f2tf(v.x));
        spk[a_idx_local(r, col4 * 4 + 1)] = __uint_as_float(f2tf(v.y));
        spk[a_idx_local(r, col4 * 4 + 2)] = __uint_as_float(f2tf(v.z));
        spk[a_idx_local(r, col4 * 4 + 3)] = __uint_as_float(f2tf(v.w));
    }
    __syncthreads();
    size_t base = ((size_t)blockIdx.y * (K >> 5) + blockIdx.x) * 4096;
    float4* o = (float4*)&out[base];
    const float4* s4 = (const float4*)spk;
    #pragma unroll
    for (int j = 0; j < 4; j++) o[tid + j * 256] = s4[tid + j * 256];
}

// ---- W[K][N] -> packed-B tf32 (logical W^T), smem-staged ----
__global__ __launch_bounds__(256) void pack_b_kernel(
    const float* __restrict__ W, float* __restrict__ out, int K, int N)
{
    __shared__ float spk[4096];
    const int tid = threadIdx.x;
    const int n0 = blockIdx.x * 128, k0 = blockIdx.y * 32;
    const int nc4 = tid & 31, kr0 = tid >> 5;
    #pragma unroll
    for (int rep = 0; rep < 4; rep++) {
        int kr = kr0 + rep * 8;
        float4 v = *(const float4*)&W[(size_t)(k0 + kr) * N + n0 + nc4 * 4];
        spk[b_idx_local(nc4 * 4 + 0, kr)] = __uint_as_float(f2tf(v.x));
        spk[b_idx_local(nc4 * 4 + 1, kr)] = __uint_as_float(f2tf(v.y));
        spk[b_idx_local(nc4 * 4 + 2, kr)] = __uint_as_float(f2tf(v.z));
        spk[b_idx_local(nc4 * 4 + 3, kr)] = __uint_as_float(f2tf(v.w));
    }
    __syncthreads();
    size_t base = ((size_t)blockIdx.x * (K >> 5) + blockIdx.y) * 4096;
    float4* o = (float4*)&out[base];
    const float4* s4 = (const float4*)spk;
    #pragma unroll
    for (int j = 0; j < 4; j++) o[tid + j * 256] = s4[tid + j * 256];
}

// ============================================================================
// TF32 mma.sync GEMM, fragment-packed operands, 3-stage cp.async pipeline.
// ============================================================================
#define TILE_F 4096
#define GEMM_SMEM (6 * TILE_F * 4)        // 96 KB

__device__ __forceinline__ void cp16(void* smem, const void* gmem) {
    uint32_t s = (uint32_t)__cvta_generic_to_shared(smem);
    asm volatile("cp.async.cg.shared.global [%0], [%1], 16;" :: "r"(s), "l"(gmem));
}
__device__ __forceinline__ void mma_tf32(float* c, const uint32_t* a, const uint32_t* b) {
    asm volatile("mma.sync.aligned.m16n8k8.row.col.f32.tf32.tf32.f32 "
        "{%0,%1,%2,%3}, {%4,%5,%6,%7}, {%8,%9}, {%0,%1,%2,%3};"
        : "+f"(c[0]), "+f"(c[1]), "+f"(c[2]), "+f"(c[3])
        : "r"(a[0]), "r"(a[1]), "r"(a[2]), "r"(a[3]), "r"(b[0]), "r"(b[1]));
}

template<int MODE>
__global__ __launch_bounds__(128, 2) void tc_gemm(
    const float* __restrict__ Ap, const float* __restrict__ Bp,
    float* __restrict__ Cp, int M, int N, int K)
{
    extern __shared__ float sm[];
    float* As = sm;                 // [3][TILE_F]
    float* Bs = sm + 3 * TILE_F;

    const int tid = threadIdx.x;
    const int bx = blockIdx.x, by = blockIdx.y;
    const int warp = tid >> 5, lane = tid & 31;
    const int wm = warp & 1, wn = warp >> 1;

    const int NKT = K >> 5;
    const float* Atile = Ap + (size_t)by * NKT * TILE_F;
    const float* Btile = Bp + (size_t)bx * NKT * TILE_F;

    float acc[4][8][4];
    #pragma unroll
    for (int i = 0; i < 4; i++)
        #pragma unroll
        for (int j = 0; j < 8; j++)
            #pragma unroll
            for (int q = 0; q < 4; q++) acc[i][j][q] = 0.f;

    auto prefetch = [&](int st, int kt) {
        const float* ag = Atile + (size_t)kt * TILE_F;
        const float* bg = Btile + (size_t)kt * TILE_F;
        float* asd = As + st * TILE_F;
        float* bsd = Bs + st * TILE_F;
        #pragma unroll
        for (int i = 0; i < 8; i++) {
            int c = (tid + i * 128) * 4;
            cp16(&asd[c], &ag[c]);
        }
        #pragma unroll
        for (int i = 0; i < 8; i++) {
            int c = (tid + i * 128) * 4;
            cp16(&bsd[c], &bg[c]);
        }
        asm volatile("cp.async.commit_group;");
    };

    prefetch(0, 0);
    if (NKT > 1) prefetch(1, 1);

    int st = 0;
    for (int it = 0; it < NKT; it++) {
        if (it + 1 < NKT) asm volatile("cp.async.wait_group 1;");
        else              asm volatile("cp.async.wait_group 0;");
        __syncthreads();
        if (it + 2 < NKT) {
            int nstage = st + 2; if (nstage >= 3) nstage -= 3;
            prefetch(nstage, it + 2);
        }

        const uint4* A4 = (const uint4*)(As + st * TILE_F);
        const uint4* B4 = (const uint4*)(Bs + st * TILE_F);

        uint4 a4[2][4], b4[2][4];
        #pragma unroll
        for (int mf = 0; mf < 4; mf++) a4[0][mf] = A4[((0 * 2 + wm) * 4 + mf) * 32 + lane];
        #pragma unroll
        for (int j = 0; j < 4; j++)   b4[0][j]  = B4[((0 * 2 + wn) * 4 + j) * 32 + lane];

        #pragma unroll
        for (int ks = 0; ks < 4; ks++) {
            const int cur = ks & 1, nxt = cur ^ 1;
            if (ks < 3) {
                #pragma unroll
                for (int mf = 0; mf < 4; mf++)
                    a4[nxt][mf] = A4[(((ks + 1) * 2 + wm) * 4 + mf) * 32 + lane];
                #pragma unroll
                for (int j = 0; j < 4; j++)
                    b4[nxt][j] = B4[(((ks + 1) * 2 + wn) * 4 + j) * 32 + lane];
            }
            uint32_t af[4][4], bf[8][2];
            #pragma unroll
            for (int mf = 0; mf < 4; mf++) {
                af[mf][0] = a4[cur][mf].x; af[mf][1] = a4[cur][mf].y;
                af[mf][2] = a4[cur][mf].z; af[mf][3] = a4[cur][mf].w;
            }
            #pragma unroll
            for (int j = 0; j < 4; j++) {
                bf[2*j][0] = b4[cur][j].x; bf[2*j][1] = b4[cur][j].y;
                bf[2*j+1][0] = b4[cur][j].z; bf[2*j+1][1] = b4[cur][j].w;
            }
            #pragma unroll
            for (int mf = 0; mf < 4; mf++)
                #pragma unroll
                for (int nf = 0; nf < 8; nf++)
                    mma_tf32(acc[mf][nf], af[mf], bf[nf]);
        }

        if (++st >= 3) st = 0;
    }

    // ---- epilogue ----
    const int gid = lane >> 2, tig = lane & 3;
    const int row0 = by * 128 + wm * 64;
    const int col0 = bx * 128 + wn * 64;
    #pragma unroll
    for (int mf = 0; mf < 4; mf++) {
        #pragma unroll
        for (int nf = 0; nf < 8; nf++) {
            int r = row0 + mf * 16 + gid;
            int c = col0 + nf * 8 + tig * 2;
            float2 v0 = make_float2(acc[mf][nf][0], acc[mf][nf][1]);
            float2 v1 = make_float2(acc[mf][nf][2], acc[mf][nf][3]);
            if (MODE == 0) {
                if (c < DINNER) {
                    *(float2*)&g_xmain[(size_t)r * DINNER + c] = v0;
                    *(float2*)&g_xmain[(size_t)(r + 8) * DINNER + c] = v1;
                } else {
                    int c2 = c - DINNER;
                    *(float2*)&g_sres[(size_t)r * DINNER + c2] =
                        make_float2(silu(v0.x), silu(v0.y));
                    *(float2*)&g_sres[(size_t)(r + 8) * DINNER + c2] =
                        make_float2(silu(v1.x), silu(v1.y));
                }
            } else {
                *(float2*)&Cp[(size_t)r * N + c] = v0;
                *(float2*)&Cp[(size_t)(r + 8) * N + c] = v1;
            }
        }
    }
}

// ============================================================================
// Split conv_proj: grid (NTOK/64, NSPLIT). Each block: conv+SiLU for its
// 64 tokens x 512 channels, writes g_xc, accumulates partial B/C proj.
// ============================================================================
#define TT 64
#define KC 64

__global__ __launch_bounds__(256) void conv_proj_kernel(
    const float* __restrict__ cw, const float* __restrict__ cb,
    const float* __restrict__ WB, const float* __restrict__ WC)
{
    __shared__ float sxc[TT][KC + 1];
    __shared__ float sW[KC][32];

    const int tid = threadIdx.x;
    const int t0 = blockIdx.x * TT;
    const int split = blockIdx.y;

    const int tx = tid & 7;            // stage-2: output group (4 outs)
    const int ty = tid >> 3;           // stage-2: token group (2 tokens)

    float acc[2][4];
    #pragma unroll
    for (int i = 0; i < 2; i++)
        #pragma unroll
        for (int j = 0; j < 4; j++) acc[i][j] = 0.f;

    const int ch_l = tid & 63;         // stage-1 channel lane
    const int tg = tid >> 6;           // stage-1 token group (4 x 16)

    for (int cc = 0; cc < KSPL; cc += KC) {
        const int c0 = split * KSPL + cc;

        // ---- load W chunk [KC][32] ----
        #pragma unroll
        for (int rep = 0; rep < 2; rep++) {
            int idx = tid + rep * 256;
            int ch = idx >> 3;
            int j = idx & 7;
            float4 v;
            if (j < 4) v = *(const float4*)&WB[(size_t)(c0 + ch) * DSTATE + 4 * j];
            else       v = *(const float4*)&WC[(size_t)(c0 + ch) * DSTATE + 4 * (j - 4)];
            *(float4*)&sW[ch][4 * j] = v;
        }

        // ---- stage 1: conv + silu for 64 tokens x 64 channels ----
        {
            int ch = c0 + ch_l;
            float w0 = cw[ch * 3 + 0], w1 = cw[ch * 3 + 1], w2 = cw[ch * 3 + 2];
            float cbv = cb[ch];
            int tt = t0 + tg * 16;
            const float* xm = g_xmain + (size_t)tt * DINNER + ch;
            float cur = xm[0];
            float prev = ((tt & (SEQ - 1)) == 0) ? 0.f : xm[-(int)DINNER];
            float* xcg = g_xc + (size_t)tt * DINNER + ch;
            #pragma unroll 4
            for (int i = 0; i < 16; i++) {
                int tcur = tt + i;
                float nxt = ((tcur & (SEQ - 1)) == SEQ - 1) ? 0.f
                            : xm[(size_t)(i + 1) * DINNER];
                float v = cbv + prev * w0 + cur * w1 + nxt * w2;
                float xc = silu(v);
                sxc[tg * 16 + i][ch_l] = xc;
                xcg[(size_t)i * DINNER] = xc;
                prev = cur; cur = nxt;
            }
        }
        __syncthreads();

        // ---- stage 2: acc += sxc @ sW ----
        #pragma unroll 4
        for (int k = 0; k < KC; k++) {
            float rb[4];
            *(float4*)rb = *(const float4*)&sW[k][tx * 4];
            float ra[2];
            #pragma unroll
            for (int i = 0; i < 2; i++) ra[i] = sxc[ty * 2 + i][k];
            #pragma unroll
            for (int i = 0; i < 2; i++)
                #pragma unroll
                for (int j = 0; j < 4; j++)
                    acc[i][j] += ra[i] * rb[j];
        }
        __syncthreads();
    }

    // ---- write partials: g_part[split][token][32] ----
    #pragma unroll
    for (int i = 0; i < 2; i++) {
        int t = t0 + ty * 2 + i;
        float* dst = &g_part[((size_t)split * NTOK + t) * 32 + tx * 4];
        *(float4*)dst = *(float4*)acc[i];
    }
}

// ---- sum the NSPLIT partials into g_B / g_C ----
__global__ __launch_bounds__(256) void reduce_bc_kernel()
{
    int i = blockIdx.x * 256 + threadIdx.x;      // 0 .. NTOK*32-1
    if (i >= NTOK * 32) return;
    float v = 0.f;
    #pragma unroll
    for (int p = 0; p < NSPLIT; p++) v += g_part[(size_t)p * NTOK * 32 + i];
    int tok = i >> 5, s = i & 31;
    if (s < DSTATE) g_B[tok * DSTATE + s] = v;
    else            g_C[tok * DSTATE + (s - DSTATE)] = v;
}

// ============================================================================
// scan
// ============================================================================
__global__ void decay_kernel(const float* __restrict__ A)
{
    int s = threadIdx.x;
    if (s < DSTATE) {
        float d = 1.f / (1.f + __expf(A[s]));
        g_decay[s] = d;
        float x = d;
        #pragma unroll
        for (int i = 0; i < 6; i++) x *= x;
        g_dCH[s] = x;
        g_l2d[s] = log2f(d);
    }
}

__global__ __launch_bounds__(256) void scan_local_kernel()
{
    int id = blockIdx.x * 256 + threadIdx.x;
    int s = id & (DSTATE - 1);
    int cg = id >> 4;
    int b = cg / NCHUNK, c = cg % NCHUNK;
    float d = g_decay[s];
    size_t base = ((size_t)b * SEQ + (size_t)c * SCHUNK) * DSTATE + s;
    float S = 0.f;
    #pragma unroll 4
    for (int t = 0; t < SCHUNK; t++) {
        S = S * d + g_B[base + (size_t)t * DSTATE];
        g_loc[base + (size_t)t * DSTATE] = S;
    }
    g_E[cg * DSTATE + s] = S;
}

__global__ void scan_carry_kernel()
{
    int id = threadIdx.x;
    if (id >= BATCH * DSTATE) return;
    int b = id / DSTATE, s = id % DSTATE;
    float dch = g_dCH[s];
    float S = 0.f;
    for (int c = 0; c < NCHUNK; c++) {
        g_Sinit[(b * NCHUNK + c) * DSTATE + s] = S;
        S = S * dch + g_E[(b * NCHUNK + c) * DSTATE + s];
    }
}

__global__ __launch_bounds__(256) void scan_output_kernel()
{
    __shared__ float sl2d[DSTATE];
    int tid = threadIdx.x;
    if (tid < DSTATE) sl2d[tid] = g_l2d[tid];
    __syncthreads();

    int t = blockIdx.x * 256 + tid;
    int b = t >> 12;
    int c = (t & (SEQ - 1)) >> 6;
    int tl = t & (SCHUNK - 1);
    const float* sinit = &g_Sinit[(b * NCHUNK + c) * DSTATE];

    float ys = 0.f;
    float tp1 = (float)(tl + 1);
    #pragma unroll
    for (int q = 0; q < 4; q++) {
        float4 lo = *(const float4*)&g_loc[(size_t)t * DSTATE + q * 4];
        float4 cc = *(const float4*)&g_C  [(size_t)t * DSTATE + q * 4];
        float4 si = *(const float4*)&sinit[q * 4];
        float d0 = exp2f(tp1 * sl2d[q*4+0]);
        float d1 = exp2f(tp1 * sl2d[q*4+1]);
        float d2 = exp2f(tp1 * sl2d[q*4+2]);
        float d3 = exp2f(tp1 * sl2d[q*4+3]);
        ys += (lo.x + d0 * si.x) * cc.x;
        ys += (lo.y + d1 * si.y) * cc.y;
        ys += (lo.z + d2 * si.z) * cc.z;
        ys += (lo.w + d3 * si.w) * cc.w;
    }
    g_ys[t] = ys;
}

// ---- gate + pack-A, smem-staged ----
__global__ __launch_bounds__(256) void gate_pack_kernel(const float* __restrict__ Dp)
{
    __shared__ float spk[4096];
    const int tid = threadIdx.x;
    const int ch0 = blockIdx.x * 32, t0 = blockIdx.y * 128;
    const int col4 = tid & 7, r0 = tid >> 3;
    float4 dd = *(const float4*)&Dp[ch0 + col4 * 4];
    #pragma unroll
    for (int rep = 0; rep < 4; rep++) {
        int r = r0 + rep * 32;
        int tok = t0 + r;
        size_t off = (size_t)tok * DINNER + ch0 + col4 * 4;
        float4 xc = *(const float4*)&g_xc[off];
        float4 sr = *(const float4*)&g_sres[off];
        float ys = g_ys[tok];
        spk[a_idx_local(r, col4 * 4 + 0)] = __uint_as_float(f2tf((ys + xc.x * dd.x) * sr.x));
        spk[a_idx_local(r, col4 * 4 + 1)] = __uint_as_float(f2tf((ys + xc.y * dd.y) * sr.y));
        spk[a_idx_local(r, col4 * 4 + 2)] = __uint_as_float(f2tf((ys + xc.z * dd.z) * sr.z));
        spk[a_idx_local(r, col4 * 4 + 3)] = __uint_as_float(f2tf((ys + xc.w * dd.w) * sr.w));
    }
    __syncthreads();
    size_t base = ((size_t)blockIdx.y * (DINNER >> 5) + blockIdx.x) * 4096;
    float4* o = (float4*)&g_y[base];
    const float4* s4 = (const float4*)spk;
    #pragma unroll
    for (int j = 0; j < 4; j++) o[tid + j * 256] = s4[tid + j * 256];
}

// ============================================================================
extern "C" void kernel_launch(void* const* d_in, const int* in_sizes, int n_in,
                              void* d_out, int out_size)
{
    const float* x      = (const float*)d_in[0];
    const float* W_in   = (const float*)d_in[1];
    const float* conv_w = (const float*)d_in[2];
    const float* conv_b = (const float*)d_in[3];
    const float* W_B    = (const float*)d_in[4];
    const float* W_C    = (const float*)d_in[5];
    const float* A      = (const float*)d_in[6];
    const float* Dp     = (const float*)d_in[7];
    const float* W_out  = (const float*)d_in[8];
    float* out = (float*)d_out;

    static int attr_done = 0;
    if (!attr_done) {
        cudaFuncSetAttribute(tc_gemm<0>, cudaFuncAttributeMaxDynamicSharedMemorySize, GEMM_SMEM);
        cudaFuncSetAttribute(tc_gemm<1>, cudaFuncAttributeMaxDynamicSharedMemorySize, GEMM_SMEM);
        attr_done = 1;
    }

    float* xr   = nullptr; cudaGetSymbolAddress((void**)&xr,   g_xr);
    float* win  = nullptr; cudaGetSymbolAddress((void**)&win,  g_win);
    float* wout = nullptr; cudaGetSymbolAddress((void**)&wout, g_wout);
    float* yptr = nullptr; cudaGetSymbolAddress((void**)&yptr, g_y);

    {
        dim3 g(DMODEL / 32, NTOK / 128);
        pack_a_kernel<<<g, 256>>>(x, xr, DMODEL);                        // 1
    }
    {
        dim3 g(2 * DINNER / 128, DMODEL / 32);
        pack_b_kernel<<<g, 256>>>(W_in, win, DMODEL, 2 * DINNER);        // 2
    }

    // GEMM1 (3rd): [16384,1024] x [1024 -> 4096]
    {
        dim3 grid1(2 * DINNER / 128, NTOK / 128);
        tc_gemm<0><<<grid1, 128, GEMM_SMEM>>>(xr, win, nullptr, NTOK, 2 * DINNER, DMODEL);
    }

    // conv_proj (4th, profiled): split over 4 channel groups
    {
        dim3 g(NTOK / TT, NSPLIT);
        conv_proj_kernel<<<g, 256>>>(conv_w, conv_b, W_B, W_C);
    }
    reduce_bc_kernel<<<(NTOK * 32 + 255) / 256, 256>>>();

    decay_kernel<<<1, 32>>>(A);
    scan_local_kernel<<<BATCH * NCHUNK * DSTATE / 256, 256>>>();
    scan_carry_kernel<<<1, 64>>>();
    scan_output_kernel<<<NTOK / 256, 256>>>();

    {
        dim3 g(DMODEL / 128, DINNER / 32);
        pack_b_kernel<<<g, 256>>>(W_out, wout, DINNER, DMODEL);
    }
    {
        dim3 g(DINNER / 32, NTOK / 128);
        gate_pack_kernel<<<g, 256>>>(Dp);
    }

    // GEMM2: [16384,2048] x [2048 -> 1024]
    {
        dim3 grid2(DMODEL / 128, NTOK / 128);
        tc_gemm<1><<<grid2, 128, GEMM_SMEM>>>(yptr, wout, out, NTOK, DMODEL, DINNER);
    }
}

// round 11
// speedup vs baseline: 1.5050x; 1.5050x over previous
#include <cuda_runtime.h>
#include <math.h>
#include <stdint.h>

#define BATCH  4
#define SEQ    4096
#define DMODEL 1024
#define DINNER 2048
#define DSTATE 16
#define NTOK   (BATCH*SEQ)     // 16384
#define SCHUNK 64
#define NCHUNK (SEQ/SCHUNK)    // 64
#define NSPLIT 4
#define KSPL   (DINNER/NSPLIT) // 512

// ---- scratch (device globals; no allocations allowed) ----
__device__ float g_xmain[(size_t)NTOK*DINNER];
__device__ float g_sres [(size_t)NTOK*DINNER];
__device__ float g_xc   [(size_t)NTOK*DINNER];
__device__ float g_y    [(size_t)NTOK*DINNER];     // packed-A tf32 (gate output)
__device__ float g_xr   [(size_t)NTOK*DMODEL];     // packed-A tf32 x
__device__ float g_win  [(size_t)2*DINNER*DMODEL]; // packed-B tf32 W_in^T
__device__ float g_wout [(size_t)DMODEL*DINNER];   // packed-B tf32 W_out^T
__device__ float g_part [(size_t)NSPLIT*NTOK*32];  // partial B/C projections
__device__ float g_B    [NTOK*DSTATE];
__device__ float g_C    [NTOK*DSTATE];
__device__ float g_loc  [NTOK*DSTATE];
__device__ float g_E    [BATCH*NCHUNK*DSTATE];
__device__ float g_Sinit[BATCH*NCHUNK*DSTATE];
__device__ float g_ys   [NTOK];
__device__ float g_decay[DSTATE];
__device__ float g_dCH  [DSTATE];
__device__ float g_l2d  [DSTATE];

__device__ __forceinline__ float silu(float v) { return v / (1.f + __expf(-v)); }
__device__ __forceinline__ uint32_t f2tf(float x) {
    uint32_t r; asm("cvt.rna.tf32.f32 %0, %1;" : "=r"(r) : "f"(x)); return r;
}

// ============================================================================
// Fragment-packed layouts for mma.sync.m16n8k8 (row.col).
// ============================================================================
__device__ __forceinline__ int a_idx_local(int mi, int ki) {
    int wm = mi >> 6, r6 = mi & 63, mf = r6 >> 4, rr = mi & 15;
    int gid = rr & 7, rowhalf = rr >> 3;
    int ks = ki >> 3, k8 = ki & 7, tig = k8 & 3, khalf = k8 >> 2;
    int lane = gid * 4 + tig, comp = rowhalf + 2 * khalf;
    return (((ks * 2 + wm) * 4 + mf) * 32 + lane) * 4 + comp;
}
__device__ __forceinline__ int b_idx_local(int ni, int ki) {
    int wn = ni >> 6, r6 = ni & 63, nf = r6 >> 3, gid = r6 & 7;
    int j = nf >> 1, nhalf = nf & 1;
    int ks = ki >> 3, k8 = ki & 7, tig = k8 & 3, khalf = k8 >> 2;
    int lane = gid * 4 + tig, comp = nhalf * 2 + khalf;
    return (((ks * 2 + wn) * 4 + j) * 32 + lane) * 4 + comp;
}

// ---- x -> packed-A tf32, smem-staged ----
__global__ __launch_bounds__(256) void pack_a_kernel(
    const float* __restrict__ in, float* __restrict__ out, int K)
{
    __shared__ float spk[4096];
    const int tid = threadIdx.x;
    const int ch0 = blockIdx.x * 32, m0 = blockIdx.y * 128;
    const int col4 = tid & 7, r0 = tid >> 3;
    #pragma unroll
    for (int rep = 0; rep < 4; rep++) {
        int r = r0 + rep * 32;
        float4 v = *(const float4*)&in[(size_t)(m0 + r) * K + ch0 + col4 * 4];
        spk[a_idx_local(r, col4 * 4 + 0)] = __uint_as_float(f2tf(v.x));
        spk[a_idx_local(r, col4 * 4 + 1)] = __uint_as_float(f2tf(v.y));
        spk[a_idx_local(r, col4 * 4 + 2)] = __uint_as_float(f2tf(v.z));
        spk[a_idx_local(r, col4 * 4 + 3)] = __uint_as_float(f2tf(v.w));
    }
    __syncthreads();
    size_t base = ((size_t)blockIdx.y * (K >> 5) + blockIdx.x) * 4096;
    float4* o = (float4*)&out[base];
    const float4* s4 = (const float4*)spk;
    #pragma unroll
    for (int j = 0; j < 4; j++) o[tid + j * 256] = s4[tid + j * 256];
}

// ---- W[K][N] -> packed-B tf32 (logical W^T), smem-staged ----
__global__ __launch_bounds__(256) void pack_b_kernel(
    const float* __restrict__ W, float* __restrict__ out, int K, int N)
{
    __shared__ float spk[4096];
    const int tid = threadIdx.x;
    const int n0 = blockIdx.x * 128, k0 = blockIdx.y * 32;
    const int nc4 = tid & 31, kr0 = tid >> 5;
    #pragma unroll
    for (int rep = 0; rep < 4; rep++) {
        int kr = kr0 + rep * 8;
        float4 v = *(const float4*)&W[(size_t)(k0 + kr) * N + n0 + nc4 * 4];
        spk[b_idx_local(nc4 * 4 + 0, kr)] = __uint_as_float(f2tf(v.x));
        spk[b_idx_local(nc4 * 4 + 1, kr)] = __uint_as_float(f2tf(v.y));
        spk[b_idx_local(nc4 * 4 + 2, kr)] = __uint_as_float(f2tf(v.z));
        spk[b_idx_local(nc4 * 4 + 3, kr)] = __uint_as_float(f2tf(v.w));
    }
    __syncthreads();
    size_t base = ((size_t)blockIdx.x * (K >> 5) + blockIdx.y) * 4096;
    float4* o = (float4*)&out[base];
    const float4* s4 = (const float4*)spk;
    #pragma unroll
    for (int j = 0; j < 4; j++) o[tid + j * 256] = s4[tid + j * 256];
}

// ============================================================================
// TF32 mma.sync GEMM, fragment-packed operands, 3-stage cp.async pipeline.
// ============================================================================
#define TILE_F 4096
#define GEMM_SMEM (6 * TILE_F * 4)        // 96 KB

__device__ __forceinline__ void cp16(void* smem, const void* gmem) {
    uint32_t s = (uint32_t)__cvta_generic_to_shared(smem);
    asm volatile("cp.async.cg.shared.global [%0], [%1], 16;" :: "r"(s), "l"(gmem));
}
__device__ __forceinline__ void mma_tf32(float* c, const uint32_t* a, const uint32_t* b) {
    asm volatile("mma.sync.aligned.m16n8k8.row.col.f32.tf32.tf32.f32 "
        "{%0,%1,%2,%3}, {%4,%5,%6,%7}, {%8,%9}, {%0,%1,%2,%3};"
        : "+f"(c[0]), "+f"(c[1]), "+f"(c[2]), "+f"(c[3])
        : "r"(a[0]), "r"(a[1]), "r"(a[2]), "r"(a[3]), "r"(b[0]), "r"(b[1]));
}

template<int MODE>
__global__ __launch_bounds__(128, 2) void tc_gemm(
    const float* __restrict__ Ap, const float* __restrict__ Bp,
    float* __restrict__ Cp, int M, int N, int K)
{
    extern __shared__ float sm[];
    float* As = sm;                 // [3][TILE_F]
    float* Bs = sm + 3 * TILE_F;

    const int tid = threadIdx.x;
    const int bx = blockIdx.x, by = blockIdx.y;
    const int warp = tid >> 5, lane = tid & 31;
    const int wm = warp & 1, wn = warp >> 1;

    const int NKT = K >> 5;
    const float* Atile = Ap + (size_t)by * NKT * TILE_F;
    const float* Btile = Bp + (size_t)bx * NKT * TILE_F;

    float acc[4][8][4];
    #pragma unroll
    for (int i = 0; i < 4; i++)
        #pragma unroll
        for (int j = 0; j < 8; j++)
            #pragma unroll
            for (int q = 0; q < 4; q++) acc[i][j][q] = 0.f;

    auto prefetch = [&](int st, int kt) {
        const float* ag = Atile + (size_t)kt * TILE_F;
        const float* bg = Btile + (size_t)kt * TILE_F;
        float* asd = As + st * TILE_F;
        float* bsd = Bs + st * TILE_F;
        #pragma unroll
        for (int i = 0; i < 8; i++) {
            int c = (tid + i * 128) * 4;
            cp16(&asd[c], &ag[c]);
        }
        #pragma unroll
        for (int i = 0; i < 8; i++) {
            int c = (tid + i * 128) * 4;
            cp16(&bsd[c], &bg[c]);
        }
        asm volatile("cp.async.commit_group;");
    };

    prefetch(0, 0);
    if (NKT > 1) prefetch(1, 1);

    int st = 0;
    for (int it = 0; it < NKT; it++) {
        if (it + 1 < NKT) asm volatile("cp.async.wait_group 1;");
        else              asm volatile("cp.async.wait_group 0;");
        __syncthreads();
        if (it + 2 < NKT) {
            int nstage = st + 2; if (nstage >= 3) nstage -= 3;
            prefetch(nstage, it + 2);
        }

        const uint4* A4 = (const uint4*)(As + st * TILE_F);
        const uint4* B4 = (const uint4*)(Bs + st * TILE_F);

        uint4 a4[2][4], b4[2][4];
        #pragma unroll
        for (int mf = 0; mf < 4; mf++) a4[0][mf] = A4[((0 * 2 + wm) * 4 + mf) * 32 + lane];
        #pragma unroll
        for (int j = 0; j < 4; j++)   b4[0][j]  = B4[((0 * 2 + wn) * 4 + j) * 32 + lane];

        #pragma unroll
        for (int ks = 0; ks < 4; ks++) {
            const int cur = ks & 1, nxt = cur ^ 1;
            if (ks < 3) {
                #pragma unroll
                for (int mf = 0; mf < 4; mf++)
                    a4[nxt][mf] = A4[(((ks + 1) * 2 + wm) * 4 + mf) * 32 + lane];
                #pragma unroll
                for (int j = 0; j < 4; j++)
                    b4[nxt][j] = B4[(((ks + 1) * 2 + wn) * 4 + j) * 32 + lane];
            }
            uint32_t af[4][4], bf[8][2];
            #pragma unroll
            for (int mf = 0; mf < 4; mf++) {
                af[mf][0] = a4[cur][mf].x; af[mf][1] = a4[cur][mf].y;
                af[mf][2] = a4[cur][mf].z; af[mf][3] = a4[cur][mf].w;
            }
            #pragma unroll
            for (int j = 0; j < 4; j++) {
                bf[2*j][0] = b4[cur][j].x; bf[2*j][1] = b4[cur][j].y;
                bf[2*j+1][0] = b4[cur][j].z; bf[2*j+1][1] = b4[cur][j].w;
            }
            #pragma unroll
            for (int mf = 0; mf < 4; mf++)
                #pragma unroll
                for (int nf = 0; nf < 8; nf++)
                    mma_tf32(acc[mf][nf], af[mf], bf[nf]);
        }

        if (++st >= 3) st = 0;
    }

    // ---- epilogue ----
    const int gid = lane >> 2, tig = lane & 3;
    const int row0 = by * 128 + wm * 64;
    const int col0 = bx * 128 + wn * 64;
    #pragma unroll
    for (int mf = 0; mf < 4; mf++) {
        #pragma unroll
        for (int nf = 0; nf < 8; nf++) {
            int r = row0 + mf * 16 + gid;
            int c = col0 + nf * 8 + tig * 2;
            float2 v0 = make_float2(acc[mf][nf][0], acc[mf][nf][1]);
            float2 v1 = make_float2(acc[mf][nf][2], acc[mf][nf][3]);
            if (MODE == 0) {
                if (c < DINNER) {
                    *(float2*)&g_xmain[(size_t)r * DINNER + c] = v0;
                    *(float2*)&g_xmain[(size_t)(r + 8) * DINNER + c] = v1;
                } else {
                    int c2 = c - DINNER;
                    *(float2*)&g_sres[(size_t)r * DINNER + c2] =
                        make_float2(silu(v0.x), silu(v0.y));
                    *(float2*)&g_sres[(size_t)(r + 8) * DINNER + c2] =
                        make_float2(silu(v1.x), silu(v1.y));
                }
            } else {
                *(float2*)&Cp[(size_t)r * N + c] = v0;
                *(float2*)&Cp[(size_t)(r + 8) * N + c] = v1;
            }
        }
    }
}

// ============================================================================
// Split conv_proj: grid (NTOK/128, NSPLIT). Each block: conv+SiLU for its
// 128 tokens x 512 channels, writes g_xc, accumulates partial B/C proj.
// ============================================================================
#define TT 128
#define KC 64

__global__ __launch_bounds__(256) void conv_proj_kernel(
    const float* __restrict__ cw, const float* __restrict__ cb,
    const float* __restrict__ WB, const float* __restrict__ WC)
{
    __shared__ float sxc[TT][KC + 1];
    __shared__ float sW[KC][32];

    const int tid = threadIdx.x;
    const int t0 = blockIdx.x * TT;
    const int split = blockIdx.y;

    const int tx = tid & 7;            // stage-2: output group (4 outs)
    const int ty = tid >> 3;           // stage-2: token group (4 tokens)

    float acc[4][4];
    #pragma unroll
    for (int i = 0; i < 4; i++)
        #pragma unroll
        for (int j = 0; j < 4; j++) acc[i][j] = 0.f;

    const int ch_l = tid & 63;         // stage-1 channel lane
    const int tg = tid >> 6;           // stage-1 token group (4 x 32)

    for (int cc = 0; cc < KSPL; cc += KC) {
        const int c0 = split * KSPL + cc;

        // ---- load W chunk [KC][32] ----
        #pragma unroll
        for (int rep = 0; rep < 2; rep++) {
            int idx = tid + rep * 256;
            int ch = idx >> 3;
            int j = idx & 7;
            float4 v;
            if (j < 4) v = *(const float4*)&WB[(size_t)(c0 + ch) * DSTATE + 4 * j];
            else       v = *(const float4*)&WC[(size_t)(c0 + ch) * DSTATE + 4 * (j - 4)];
            *(float4*)&sW[ch][4 * j] = v;
        }

        // ---- stage 1: conv + silu for 128 tokens x 64 channels ----
        {
            int ch = c0 + ch_l;
            float w0 = cw[ch * 3 + 0], w1 = cw[ch * 3 + 1], w2 = cw[ch * 3 + 2];
            float cbv = cb[ch];
            int tt = t0 + tg * 32;
            const float* xm = g_xmain + (size_t)tt * DINNER + ch;
            float cur = xm[0];
            float prev = ((tt & (SEQ - 1)) == 0) ? 0.f : xm[-(int)DINNER];
            float* xcg = g_xc + (size_t)tt * DINNER + ch;
            #pragma unroll 4
            for (int i = 0; i < 32; i++) {
                int tcur = tt + i;
                float nxt = ((tcur & (SEQ - 1)) == SEQ - 1) ? 0.f
                            : xm[(size_t)(i + 1) * DINNER];
                float v = cbv + prev * w0 + cur * w1 + nxt * w2;
                float xc = silu(v);
                sxc[tg * 32 + i][ch_l] = xc;
                xcg[(size_t)i * DINNER] = xc;
                prev = cur; cur = nxt;
            }
        }
        __syncthreads();

        // ---- stage 2: acc += sxc @ sW ----
        #pragma unroll 4
        for (int k = 0; k < KC; k++) {
            float rb[4];
            *(float4*)rb = *(const float4*)&sW[k][tx * 4];
            float ra[4];
            #pragma unroll
            for (int i = 0; i < 4; i++) ra[i] = sxc[ty * 4 + i][k];
            #pragma unroll
            for (int i = 0; i < 4; i++)
                #pragma unroll
                for (int j = 0; j < 4; j++)
                    acc[i][j] += ra[i] * rb[j];
        }
        __syncthreads();
    }

    // ---- write partials: g_part[split][token][32] ----
    #pragma unroll
    for (int i = 0; i < 4; i++) {
        int t = t0 + ty * 4 + i;
        float* dst = &g_part[((size_t)split * NTOK + t) * 32 + tx * 4];
        *(float4*)dst = *(float4*)acc[i];
    }
}

// ---- sum the NSPLIT partials into g_B / g_C ----
__global__ __launch_bounds__(256) void reduce_bc_kernel()
{
    int i = blockIdx.x * 256 + threadIdx.x;      // 0 .. NTOK*32-1
    if (i >= NTOK * 32) return;
    float v = 0.f;
    #pragma unroll
    for (int p = 0; p < NSPLIT; p++) v += g_part[(size_t)p * NTOK * 32 + i];
    int tok = i >> 5, s = i & 31;
    if (s < DSTATE) g_B[tok * DSTATE + s] = v;
    else            g_C[tok * DSTATE + (s - DSTATE)] = v;
}

// ============================================================================
// scan
// ============================================================================
__global__ void decay_kernel(const float* __restrict__ A)
{
    int s = threadIdx.x;
    if (s < DSTATE) {
        float d = 1.f / (1.f + __expf(A[s]));
        g_decay[s] = d;
        float x = d;
        #pragma unroll
        for (int i = 0; i < 6; i++) x *= x;
        g_dCH[s] = x;
        g_l2d[s] = log2f(d);
    }
}

__global__ __launch_bounds__(256) void scan_local_kernel()
{
    int id = blockIdx.x * 256 + threadIdx.x;
    int s = id & (DSTATE - 1);
    int cg = id >> 4;
    int b = cg / NCHUNK, c = cg % NCHUNK;
    float d = g_decay[s];
    size_t base = ((size_t)b * SEQ + (size_t)c * SCHUNK) * DSTATE + s;
    float S = 0.f;
    #pragma unroll 4
    for (int t = 0; t < SCHUNK; t++) {
        S = S * d + g_B[base + (size_t)t * DSTATE];
        g_loc[base + (size_t)t * DSTATE] = S;
    }
    g_E[cg * DSTATE + s] = S;
}

__global__ void scan_carry_kernel()
{
    int id = threadIdx.x;
    if (id >= BATCH * DSTATE) return;
    int b = id / DSTATE, s = id % DSTATE;
    float dch = g_dCH[s];
    float S = 0.f;
    for (int c = 0; c < NCHUNK; c++) {
        g_Sinit[(b * NCHUNK + c) * DSTATE + s] = S;
        S = S * dch + g_E[(b * NCHUNK + c) * DSTATE + s];
    }
}

__global__ __launch_bounds__(256) void scan_output_kernel()
{
    __shared__ float sl2d[DSTATE];
    int tid = threadIdx.x;
    if (tid < DSTATE) sl2d[tid] = g_l2d[tid];
    __syncthreads();

    int t = blockIdx.x * 256 + tid;
    int b = t >> 12;
    int c = (t & (SEQ - 1)) >> 6;
    int tl = t & (SCHUNK - 1);
    const float* sinit = &g_Sinit[(b * NCHUNK + c) * DSTATE];

    float ys = 0.f;
    float tp1 = (float)(tl + 1);
    #pragma unroll
    for (int q = 0; q < 4; q++) {
        float4 lo = *(const float4*)&g_loc[(size_t)t * DSTATE + q * 4];
        float4 cc = *(const float4*)&g_C  [(size_t)t * DSTATE + q * 4];
        float4 si = *(const float4*)&sinit[q * 4];
        float d0 = exp2f(tp1 * sl2d[q*4+0]);
        float d1 = exp2f(tp1 * sl2d[q*4+1]);
        float d2 = exp2f(tp1 * sl2d[q*4+2]);
        float d3 = exp2f(tp1 * sl2d[q*4+3]);
        ys += (lo.x + d0 * si.x) * cc.x;
        ys += (lo.y + d1 * si.y) * cc.y;
        ys += (lo.z + d2 * si.z) * cc.z;
        ys += (lo.w + d3 * si.w) * cc.w;
    }
    g_ys[t] = ys;
}

// ---- gate + pack-A, smem-staged ----
__global__ __launch_bounds__(256) void gate_pack_kernel(const float* __restrict__ Dp)
{
    __shared__ float spk[4096];
    const int tid = threadIdx.x;
    const int ch0 = blockIdx.x * 32, t0 = blockIdx.y * 128;
    const int col4 = tid & 7, r0 = tid >> 3;
    float4 dd = *(const float4*)&Dp[ch0 + col4 * 4];
    #pragma unroll
    for (int rep = 0; rep < 4; rep++) {
        int r = r0 + rep * 32;
        int tok = t0 + r;
        size_t off = (size_t)tok * DINNER + ch0 + col4 * 4;
        float4 xc = *(const float4*)&g_xc[off];
        float4 sr = *(const float4*)&g_sres[off];
        float ys = g_ys[tok];
        spk[a_idx_local(r, col4 * 4 + 0)] = __uint_as_float(f2tf((ys + xc.x * dd.x) * sr.x));
        spk[a_idx_local(r, col4 * 4 + 1)] = __uint_as_float(f2tf((ys + xc.y * dd.y) * sr.y));
        spk[a_idx_local(r, col4 * 4 + 2)] = __uint_as_float(f2tf((ys + xc.z * dd.z) * sr.z));
        spk[a_idx_local(r, col4 * 4 + 3)] = __uint_as_float(f2tf((ys + xc.w * dd.w) * sr.w));
    }
    __syncthreads();
    size_t base = ((size_t)blockIdx.y * (DINNER >> 5) + blockIdx.x) * 4096;
    float4* o = (float4*)&g_y[base];
    const float4* s4 = (const float4*)spk;
    #pragma unroll
    for (int j = 0; j < 4; j++) o[tid + j * 256] = s4[tid + j * 256];
}

// ============================================================================
extern "C" void kernel_launch(void* const* d_in, const int* in_sizes, int n_in,
                              void* d_out, int out_size)
{
    const float* x      = (const float*)d_in[0];
    const float* W_in   = (const float*)d_in[1];
    const float* conv_w = (const float*)d_in[2];
    const float* conv_b = (const float*)d_in[3];
    const float* W_B    = (const float*)d_in[4];
    const float* W_C    = (const float*)d_in[5];
    const float* A      = (const float*)d_in[6];
    const float* Dp     = (const float*)d_in[7];
    const float* W_out  = (const float*)d_in[8];
    float* out = (float*)d_out;

    static int attr_done = 0;
    if (!attr_done) {
        cudaFuncSetAttribute(tc_gemm<0>, cudaFuncAttributeMaxDynamicSharedMemorySize, GEMM_SMEM);
        cudaFuncSetAttribute(tc_gemm<1>, cudaFuncAttributeMaxDynamicSharedMemorySize, GEMM_SMEM);
        attr_done = 1;
    }

    float* xr   = nullptr; cudaGetSymbolAddress((void**)&xr,   g_xr);
    float* win  = nullptr; cudaGetSymbolAddress((void**)&win,  g_win);
    float* wout = nullptr; cudaGetSymbolAddress((void**)&wout, g_wout);
    float* yptr = nullptr; cudaGetSymbolAddress((void**)&yptr, g_y);

    {
        dim3 g(DMODEL / 32, NTOK / 128);
        pack_a_kernel<<<g, 256>>>(x, xr, DMODEL);                        // 1
    }
    {
        dim3 g(2 * DINNER / 128, DMODEL / 32);
        pack_b_kernel<<<g, 256>>>(W_in, win, DMODEL, 2 * DINNER);        // 2
    }

    // GEMM1 (3rd): [16384,1024] x [1024 -> 4096]
    {
        dim3 grid1(2 * DINNER / 128, NTOK / 128);
        tc_gemm<0><<<grid1, 128, GEMM_SMEM>>>(xr, win, nullptr, NTOK, 2 * DINNER, DMODEL);
    }

    // conv_proj (4th, profiled): split over 4 channel groups, 128-token tiles
    {
        dim3 g(NTOK / TT, NSPLIT);
        conv_proj_kernel<<<g, 256>>>(conv_w, conv_b, W_B, W_C);
    }
    reduce_bc_kernel<<<(NTOK * 32 + 255) / 256, 256>>>();

    decay_kernel<<<1, 32>>>(A);
    scan_local_kernel<<<BATCH * NCHUNK * DSTATE / 256, 256>>>();
    scan_carry_kernel<<<1, 64>>>();
    scan_output_kernel<<<NTOK / 256, 256>>>();

    {
        dim3 g(DMODEL / 128, DINNER / 32);
        pack_b_kernel<<<g, 256>>>(W_out, wout, DINNER, DMODEL);
    }
    {
        dim3 g(DINNER / 32, NTOK / 128);
        gate_pack_kernel<<<g, 256>>>(Dp);
    }

    // GEMM2: [16384,2048] x [2048 -> 1024]
    {
        dim3 grid2(DMODEL / 128, NTOK / 128);
        tc_gemm<1><<<grid2, 128, GEMM_SMEM>>>(yptr, wout, out, NTOK, DMODEL, DINNER);
    }
}